// round 6
// baseline (speedup 1.0000x reference)
#include <cuda_runtime.h>
#include <math.h>

#define BATCH   64
#define NGT     32
#define NTOT    64512
#define NGROUPS 192   // 3 scales * 64 images

// ---- scratch (no allocations allowed) ----
__device__ unsigned int g_negbits[BATCH * NTOT];   // 16.5 MB, fully rewritten each run
__device__ double       g_acc;
__device__ int          g_numpos[NGROUPS];

__global__ void zero_kernel() {
    int t = threadIdx.x;
    if (t == 0) g_acc = 0.0;
    if (t < NGROUPS) g_numpos[t] = 0;
}

__device__ __forceinline__ float smooth_l1(float x) {
    float ax = fabsf(x);
    return ax < 1.0f ? (0.5f * x) * x : ax - 0.5f;
}

// One thread handles the 3 anchors (a=0..2) at one grid position (h,w).
// Per-block: precompute clamped wy per (row, gt, anchor) + per-row GT bitmask.
template<int H, int W, int STRIDE, int OFF, int SCALE>
__global__ void __launch_bounds__(256) match_kernel(const float* __restrict__ pred,
                                                    const float* __restrict__ gtb,
                                                    const int*   __restrict__ gtl)
{
    constexpr int HW   = H * W;
    constexpr int ROWS = 256 / W;           // rows covered by one block (2/4/8)
    const int b   = blockIdx.y;
    const int tid = threadIdx.x;

    __shared__ float4   sgt[NGT];
    __shared__ float    sarea[NGT];
    __shared__ int      slab[NGT];
    __shared__ float    swy[ROWS][NGT][3];  // clamped y-overlap per anchor
    __shared__ unsigned smask[ROWS];        // GTs with nonzero y-overlap (largest anchor)
    __shared__ float    swarp[8];
    __shared__ int      swpos[8];

    const float fs = (float)STRIDE;
    const float hh[3]    = {1.5f * fs, 2.0f * fs, 2.5f * fs};       // exact fp32
    const float areaA[3] = {9.0f * fs * fs, 16.0f * fs * fs, 25.0f * fs * fs};

    if (tid < NGT) {
        float4 g = ((const float4*)gtb)[b * NGT + tid];
        sgt[tid]   = g;
        sarea[tid] = (g.z - g.x) * (g.w - g.y);
        slab[tid]  = gtl[b * NGT + tid];
    }
    if (tid < ROWS) smask[tid] = 0u;
    __syncthreads();

    // build wy table + row masks: ROWS*NGT <= 256 items, one per thread
    if (tid < ROWS * NGT) {
        const int r = tid / NGT, j = tid % NGT;
        const int hR = blockIdx.x * ROWS + r;
        const float cyr = (hR + 0.5f) * fs;                         // exact fp32
        float4 g = sgt[j];
        bool any = false;
        #pragma unroll
        for (int a = 0; a < 3; a++) {
            float wy = fminf(cyr + hh[a], g.w) - fmaxf(cyr - hh[a], g.y);
            wy = fmaxf(wy, 0.f);
            swy[r][j][a] = wy;
            any |= (wy > 0.f);
        }
        if (any) atomicOr(&smask[r], 1u << j);
    }
    __syncthreads();

    const int pl = blockIdx.x * 256 + tid;   // HW multiple of 256
    const int w  = pl % W;
    const int r  = tid / W;                  // local row (warp-uniform: W >= 32)
    const float cx = (w + 0.5f) * fs;        // exact fp32

    const float x1a0 = cx - hh[0], x2a0 = cx + hh[0];
    const float x1a1 = cx - hh[1], x2a1 = cx + hh[1];
    const float x1a2 = cx - hh[2], x2a2 = cx + hh[2];

    // best per anchor: inter, denom (incl +1e-9), gt index
    float bI[3] = {0.f, 0.f, 0.f};
    float bD[3] = {1.f, 1.f, 1.f};
    int   bJ[3] = {0, 0, 0};

    unsigned m = smask[r];
    while (m) {
        const int j = __ffs(m) - 1;
        m &= m - 1;
        float4 g = sgt[j];
        // x-cull with the largest anchor (smaller anchors nested at same center)
        float wx2 = fminf(x2a2, g.z) - fmaxf(x1a2, g.x);
        if (wx2 > 0.f) {
            const float ab = sarea[j];
            const float x1s[3] = {x1a0, x1a1, x1a2};
            const float x2s[3] = {x2a0, x2a1, x2a2};
            #pragma unroll
            for (int a = 0; a < 3; a++) {
                float wx = fminf(x2s[a], g.z) - fmaxf(x1s[a], g.x);
                float inter = fmaxf(wx, 0.f) * swy[r][j][a];
                // same evaluation order as reference: ((aA + aB) - inter) + 1e-9
                float d = ((areaA[a] + ab) - inter) + 1e-9f;
                if (inter * bD[a] > bI[a] * d) { bI[a] = inter; bD[a] = d; bJ[a] = j; }
            }
        }
    }

    float lsum = 0.f;
    int   pcount = 0;
    const float* pb = pred + (size_t)b * 24 * HW + pl;

    #pragma unroll
    for (int a = 0; a < 3; a++) {
        float iou = bI[a] / bD[a];          // IEEE div, matches reference rounding
        bool pos = (iou >= 0.5f);
        bool neg = (iou <  0.4f);

        float x  = pb[(a * 8 + 4) * HW];
        float sp = log1pf(expf(-fabsf(x)));
        float Lneg = fmaxf(x, 0.f) + sp;    // BCE with target 0 (ranking value)
        g_negbits[b * NTOT + OFF + a * HW + pl] = neg ? __float_as_uint(Lneg) : 0u;

        if (pos) {
            pcount++;
            lsum += fmaxf(x, 0.f) - x + sp; // BCE with target 1

            float4 mb = sgt[bJ[a]];
            float sa = (3.0f + a) * fs;     // aw == ah == anchor size (exact)
            float gx = (mb.x + mb.z) * 0.5f;
            float gy = (mb.y + mb.w) * 0.5f;
            float gw = fmaxf(mb.z - mb.x, 1e-6f);
            float gh = fmaxf(mb.w - mb.y, 1e-6f);
            const int hR = blockIdx.x * ROWS + r;
            float cy = (hR + 0.5f) * fs;
            float ttx = (gx - cx) / sa;
            float tty = (gy - cy) / sa;
            float ttw = logf(gw / sa);
            float tth = logf(gh / sa);

            float p0 = pb[(a * 8 + 0) * HW];
            float p1 = pb[(a * 8 + 1) * HW];
            float p2 = pb[(a * 8 + 2) * HW];
            float p3 = pb[(a * 8 + 3) * HW];
            lsum += smooth_l1(p0 - ttx) + smooth_l1(p1 - tty)
                  + smooth_l1(p2 - ttw) + smooth_l1(p3 - tth);

            float q0 = pb[(a * 8 + 5) * HW];
            float q1 = pb[(a * 8 + 6) * HW];
            float q2 = pb[(a * 8 + 7) * HW];
            float mm = fmaxf(q0, fmaxf(q1, q2));
            float lse = mm + logf(expf(q0 - mm) + expf(q1 - mm) + expf(q2 - mm));
            int lab = max(slab[bJ[a]], 0);
            float psel = (lab == 0) ? q0 : ((lab == 1) ? q1 : q2);
            lsum += lse - psel;
        }
    }

    // block reduce (256 threads = 8 warps)
    int lane = tid & 31, wid = tid >> 5;
    #pragma unroll
    for (int o = 16; o; o >>= 1) {
        lsum   += __shfl_down_sync(~0u, lsum, o);
        pcount += __shfl_down_sync(~0u, pcount, o);
    }
    if (lane == 0) { swarp[wid] = lsum; swpos[wid] = pcount; }
    __syncthreads();
    if (wid == 0) {
        lsum   = (lane < 8) ? swarp[lane] : 0.f;
        pcount = (lane < 8) ? swpos[lane] : 0;
        #pragma unroll
        for (int o = 4; o; o >>= 1) {
            lsum   += __shfl_down_sync(~0u, lsum, o);
            pcount += __shfl_down_sync(~0u, pcount, o);
        }
        if (lane == 0) {
            if (lsum != 0.f) atomicAdd(&g_acc, (double)lsum);
            if (pcount)      atomicAdd(&g_numpos[SCALE * BATCH + b], pcount);
        }
    }
}

// Per (image, scale) hard-negative top-K sum via 2-level radix select on
// positive-float bit patterns. 1 block per group; data is L2-resident.
__global__ void __launch_bounds__(1024) select_kernel()
{
    const int g = blockIdx.x;             // 0..191
    const int scale = g / BATCH;
    const int b     = g % BATCH;
    const int Ns[3]   = {49152, 12288, 3072};
    const int Offs[3] = {0, 49152, 61440};
    const int N   = Ns[scale];
    const int off = Offs[scale];
    const unsigned* base = g_negbits + b * NTOT + off;
    const int K = 3 * max(1, g_numpos[g]);

    __shared__ int      hist[4096];
    __shared__ unsigned s_T;
    __shared__ int      s_need, s_b1, s_cA;
    __shared__ float    s_v2;
    __shared__ float    sred[32];

    const int tid = threadIdx.x;
    const int NT  = blockDim.x;

    // --- level 1: 2048 bins over bits[31:20] (sign=0 always; 0 == "not neg") ---
    for (int i = tid; i < 2048; i += NT) hist[i] = 0;
    __syncthreads();
    for (int i = tid; i < N; i += NT) {
        unsigned u = base[i];
        if (u) atomicAdd(&hist[u >> 20], 1);
    }
    __syncthreads();
    if (tid == 0) {
        int acc = 0, b1 = -1, cA = 0;
        for (int bin = 2047; bin >= 0; bin--) {
            int c = hist[bin]; acc += c;
            if (acc >= K) { b1 = bin; cA = acc - c; break; }
        }
        s_b1 = b1; s_cA = cA;
        if (b1 < 0) { s_T = 1u; s_need = 0; s_v2 = 0.f; }   // fewer negs than K: take all
    }
    __syncthreads();
    const int b1 = s_b1;

    if (b1 >= 0) {
        // --- level 2: 4096 bins over bits[19:8] within boundary bin ---
        for (int i = tid; i < 4096; i += NT) hist[i] = 0;
        __syncthreads();
        for (int i = tid; i < N; i += NT) {
            unsigned u = base[i];
            if (u && (int)(u >> 20) == b1) atomicAdd(&hist[(u >> 8) & 0xFFF], 1);
        }
        __syncthreads();
        if (tid == 0) {
            int K2 = K - s_cA;           // >= 1
            int acc = 0, b2 = 0, cSA = 0;
            for (int sb = 4095; sb >= 0; sb--) {
                int c = hist[sb]; acc += c;
                if (acc >= K2) { b2 = sb; cSA = acc - c; break; }
            }
            s_need = K2 - cSA;
            s_T = ((unsigned)b1 << 20) + (((unsigned)b2 + 1u) << 8);  // strictly above sub-bin
            // boundary values share 24 leading bits -> midpoint error < 2^-16 rel
            s_v2 = __uint_as_float(((unsigned)b1 << 20) | ((unsigned)b2 << 8) | 0x80u);
        }
        __syncthreads();
    }

    // --- sum values strictly above threshold, plus `need` boundary values ---
    const unsigned T = s_T;
    float sum = 0.f;
    for (int i = tid; i < N; i += NT) {
        unsigned u = base[i];
        if (u >= T) sum += __uint_as_float(u);
    }
    #pragma unroll
    for (int o = 16; o; o >>= 1) sum += __shfl_down_sync(~0u, sum, o);
    int lane = tid & 31, wid = tid >> 5;
    if (lane == 0) sred[wid] = sum;
    __syncthreads();
    if (wid == 0) {
        sum = (lane < NT / 32) ? sred[lane] : 0.f;
        #pragma unroll
        for (int o = 16; o; o >>= 1) sum += __shfl_down_sync(~0u, sum, o);
        if (lane == 0) atomicAdd(&g_acc, (double)(sum + (float)s_need * s_v2));
    }
}

__global__ void fin_kernel(float* out) {
    out[0] = (float)(g_acc * (1.0 / 64.0));
}

extern "C" void kernel_launch(void* const* d_in, const int* in_sizes, int n_in,
                              void* d_out, int out_size)
{
    // identify inputs by element count (robust to metadata ordering)
    const float *pred0 = nullptr, *pred1 = nullptr, *pred2 = nullptr, *gtb = nullptr;
    const int *gtl = nullptr;
    for (int i = 0; i < n_in; i++) {
        switch (in_sizes[i]) {
            case 25165824: pred0 = (const float*)d_in[i]; break;  // 64*24*128*128
            case 6291456:  pred1 = (const float*)d_in[i]; break;  // 64*24*64*64
            case 1572864:  pred2 = (const float*)d_in[i]; break;  // 64*24*32*32
            case 8192:     gtb   = (const float*)d_in[i]; break;  // 64*32*4
            case 2048:     gtl   = (const int*)d_in[i];   break;  // 64*32
            default: break;                                       // anchors: recomputed
        }
    }

    zero_kernel<<<1, 256>>>();
    match_kernel<128, 128,  8,     0, 0><<<dim3(64, BATCH), 256>>>(pred0, gtb, gtl);
    match_kernel< 64,  64, 16, 49152, 1><<<dim3(16, BATCH), 256>>>(pred1, gtb, gtl);
    match_kernel< 32,  32, 32, 61440, 2><<<dim3( 4, BATCH), 256>>>(pred2, gtb, gtl);
    select_kernel<<<NGROUPS, 1024>>>();
    fin_kernel<<<1, 1>>>((float*)d_out);
}

// round 9
// speedup vs baseline: 2.1130x; 2.1130x over previous
#include <cuda_runtime.h>
#include <math.h>

#define BATCH   64
#define NGT     32
#define NTOT    64512
#define NGROUPS 192   // 3 scales * 64 images

// ---- scratch (no allocations allowed) ----
__device__ unsigned int g_negbits[BATCH * NTOT];   // 16.5 MB, fully rewritten each run
__device__ double       g_acc;
__device__ int          g_numpos[NGROUPS];

__global__ void zero_kernel() {
    int t = threadIdx.x;
    if (t == 0) g_acc = 0.0;
    if (t < NGROUPS) g_numpos[t] = 0;
}

__device__ __forceinline__ float smooth_l1(float x) {
    float ax = fabsf(x);
    return ax < 1.0f ? (0.5f * x) * x : ax - 0.5f;
}

// One thread handles the 3 anchors (a=0..2) at one grid position (h,w).
// Per-block: precompute clamped wy per (row, gt, anchor) + per-row GT bitmask.
template<int H, int W, int STRIDE, int OFF, int SCALE>
__device__ __forceinline__ void match_body(int bx, int b,
                                           const float* __restrict__ pred,
                                           const float* __restrict__ gtb,
                                           const int*   __restrict__ gtl)
{
    constexpr int HW   = H * W;
    constexpr int ROWS = 256 / W;           // rows covered by one block (2/4/8)
    const int tid = threadIdx.x;

    __shared__ float4   sgt[NGT];
    __shared__ float    sarea[NGT];
    __shared__ int      slab[NGT];
    __shared__ float    swy[ROWS][NGT][3];  // clamped y-overlap per anchor
    __shared__ unsigned smask[ROWS];        // GTs with nonzero y-overlap (largest anchor)
    __shared__ float    swarp[8];
    __shared__ int      swpos[8];

    const float fs = (float)STRIDE;
    const float hh[3]    = {1.5f * fs, 2.0f * fs, 2.5f * fs};       // exact fp32
    const float areaA[3] = {9.0f * fs * fs, 16.0f * fs * fs, 25.0f * fs * fs};

    if (tid < NGT) {
        float4 g = ((const float4*)gtb)[b * NGT + tid];
        sgt[tid]   = g;
        sarea[tid] = (g.z - g.x) * (g.w - g.y);
        slab[tid]  = gtl[b * NGT + tid];
    }
    if (tid < ROWS) smask[tid] = 0u;
    __syncthreads();

    // build wy table + row masks: ROWS*NGT <= 256 items, one per thread
    if (tid < ROWS * NGT) {
        const int r = tid / NGT, j = tid % NGT;
        const int hR = bx * ROWS + r;
        const float cyr = (hR + 0.5f) * fs;                         // exact fp32
        float4 g = sgt[j];
        bool any = false;
        #pragma unroll
        for (int a = 0; a < 3; a++) {
            float wy = fminf(cyr + hh[a], g.w) - fmaxf(cyr - hh[a], g.y);
            wy = fmaxf(wy, 0.f);
            swy[r][j][a] = wy;
            any |= (wy > 0.f);
        }
        if (any) atomicOr(&smask[r], 1u << j);
    }
    __syncthreads();

    const int pl = bx * 256 + tid;           // HW multiple of 256
    const int w  = pl % W;
    const int r  = tid / W;                  // local row (warp-uniform: W >= 32)
    const float cx = (w + 0.5f) * fs;        // exact fp32

    const float x1a0 = cx - hh[0], x2a0 = cx + hh[0];
    const float x1a1 = cx - hh[1], x2a1 = cx + hh[1];
    const float x1a2 = cx - hh[2], x2a2 = cx + hh[2];

    // best per anchor: inter, denom (incl +1e-9), gt index
    float bI[3] = {0.f, 0.f, 0.f};
    float bD[3] = {1.f, 1.f, 1.f};
    int   bJ[3] = {0, 0, 0};

    unsigned m = smask[r];
    while (m) {
        const int j = __ffs(m) - 1;
        m &= m - 1;
        float4 g = sgt[j];
        // x-cull with the largest anchor (smaller anchors nested at same center)
        float wx2 = fminf(x2a2, g.z) - fmaxf(x1a2, g.x);
        if (wx2 > 0.f) {
            const float ab = sarea[j];
            const float x1s[3] = {x1a0, x1a1, x1a2};
            const float x2s[3] = {x2a0, x2a1, x2a2};
            #pragma unroll
            for (int a = 0; a < 3; a++) {
                float wx = fminf(x2s[a], g.z) - fmaxf(x1s[a], g.x);
                float inter = fmaxf(wx, 0.f) * swy[r][j][a];
                // same evaluation order as reference: ((aA + aB) - inter) + 1e-9
                float d = ((areaA[a] + ab) - inter) + 1e-9f;
                if (inter * bD[a] > bI[a] * d) { bI[a] = inter; bD[a] = d; bJ[a] = j; }
            }
        }
    }

    float lsum = 0.f;
    int   pcount = 0;
    const float* pb = pred + (size_t)b * 24 * HW + pl;

    #pragma unroll
    for (int a = 0; a < 3; a++) {
        float iou = bI[a] / bD[a];          // IEEE div, matches reference rounding
        bool pos = (iou >= 0.5f);
        bool neg = (iou <  0.4f);

        float x  = pb[(a * 8 + 4) * HW];
        float sp = log1pf(expf(-fabsf(x)));
        float Lneg = fmaxf(x, 0.f) + sp;    // BCE with target 0 (ranking value)
        g_negbits[b * NTOT + OFF + a * HW + pl] = neg ? __float_as_uint(Lneg) : 0u;

        if (pos) {
            pcount++;
            lsum += fmaxf(x, 0.f) - x + sp; // BCE with target 1

            float4 mb = sgt[bJ[a]];
            float sa = (3.0f + a) * fs;     // aw == ah == anchor size (exact)
            float gx = (mb.x + mb.z) * 0.5f;
            float gy = (mb.y + mb.w) * 0.5f;
            float gw = fmaxf(mb.z - mb.x, 1e-6f);
            float gh = fmaxf(mb.w - mb.y, 1e-6f);
            const int hR = bx * ROWS + r;
            float cy = (hR + 0.5f) * fs;
            float ttx = (gx - cx) / sa;
            float tty = (gy - cy) / sa;
            float ttw = logf(gw / sa);
            float tth = logf(gh / sa);

            float p0 = pb[(a * 8 + 0) * HW];
            float p1 = pb[(a * 8 + 1) * HW];
            float p2 = pb[(a * 8 + 2) * HW];
            float p3 = pb[(a * 8 + 3) * HW];
            lsum += smooth_l1(p0 - ttx) + smooth_l1(p1 - tty)
                  + smooth_l1(p2 - ttw) + smooth_l1(p3 - tth);

            float q0 = pb[(a * 8 + 5) * HW];
            float q1 = pb[(a * 8 + 6) * HW];
            float q2 = pb[(a * 8 + 7) * HW];
            float mm = fmaxf(q0, fmaxf(q1, q2));
            float lse = mm + logf(expf(q0 - mm) + expf(q1 - mm) + expf(q2 - mm));
            int lab = max(slab[bJ[a]], 0);
            float psel = (lab == 0) ? q0 : ((lab == 1) ? q1 : q2);
            lsum += lse - psel;
        }
    }

    // block reduce (256 threads = 8 warps)
    int lane = tid & 31, wid = tid >> 5;
    #pragma unroll
    for (int o = 16; o; o >>= 1) {
        lsum   += __shfl_down_sync(~0u, lsum, o);
        pcount += __shfl_down_sync(~0u, pcount, o);
    }
    if (lane == 0) { swarp[wid] = lsum; swpos[wid] = pcount; }
    __syncthreads();
    if (wid == 0) {
        lsum   = (lane < 8) ? swarp[lane] : 0.f;
        pcount = (lane < 8) ? swpos[lane] : 0;
        #pragma unroll
        for (int o = 4; o; o >>= 1) {
            lsum   += __shfl_down_sync(~0u, lsum, o);
            pcount += __shfl_down_sync(~0u, pcount, o);
        }
        if (lane == 0) {
            if (lsum != 0.f) atomicAdd(&g_acc, (double)lsum);
            if (pcount)      atomicAdd(&g_numpos[SCALE * BATCH + b], pcount);
        }
    }
}

// Fused: all three scales in one launch so scale-1/2 fill SMs alongside scale-0.
// blockIdx.x: [0,64) scale0, [64,80) scale1, [80,84) scale2.
__global__ void __launch_bounds__(256) match_all(const float* __restrict__ p0,
                                                 const float* __restrict__ p1,
                                                 const float* __restrict__ p2,
                                                 const float* __restrict__ gtb,
                                                 const int*   __restrict__ gtl)
{
    const int bx = blockIdx.x, b = blockIdx.y;
    if (bx < 64)      match_body<128, 128,  8,     0, 0>(bx,      b, p0, gtb, gtl);
    else if (bx < 80) match_body< 64,  64, 16, 49152, 1>(bx - 64, b, p1, gtb, gtl);
    else              match_body< 32,  32, 32, 61440, 2>(bx - 80, b, p2, gtb, gtl);
}

// Per (image, scale) hard-negative top-K sum via 2-level radix select on
// positive-float bit patterns. 1 block per group; data is L2/L1-resident.
// Histogram atomics are warp-aggregated; boundary search is a parallel
// block suffix-scan instead of a serial tid0 loop.
__global__ void __launch_bounds__(1024) select_kernel()
{
    const int g = blockIdx.x;             // 0..191
    const int scale = g / BATCH;
    const int b     = g % BATCH;
    const int Ns[3]   = {49152, 12288, 3072};
    const int Offs[3] = {0, 49152, 61440};
    const int N   = Ns[scale];
    const int off = Offs[scale];
    const unsigned* base = g_negbits + b * NTOT + off;
    const int K = 3 * max(1, g_numpos[g]);

    __shared__ int      hist[4096];
    __shared__ int      swsum[32];
    __shared__ unsigned s_T;
    __shared__ int      s_need, s_b1, s_cA;
    __shared__ float    s_v2;
    __shared__ float    sred[32];

    const int tid  = threadIdx.x;
    const int lane = tid & 31;
    const int wid  = tid >> 5;
    const int NT   = 1024;

    // ---------- level 1: 2048 bins over bits[31:20] ----------
    for (int i = tid; i < 2048; i += NT) hist[i] = 0;
    __syncthreads();
    for (int i = tid; i < N; i += NT) {
        unsigned u = base[i];
        if (u) {
            int bin = u >> 20;
            unsigned peers = __match_any_sync(__activemask(), bin);
            if ((int)(__ffs(peers) - 1) == lane)
                atomicAdd(&hist[bin], __popc(peers));
        }
    }
    __syncthreads();

    // suffix scan (descending bins), 2 bins/thread: thread t covers 2047-2t, 2046-2t
    {
        int c0 = hist[2047 - 2 * tid];
        int c1 = hist[2046 - 2 * tid];
        int tot = c0 + c1;
        // inclusive warp scan in t-order (== descending bin order)
        int sc = tot;
        #pragma unroll
        for (int o = 1; o < 32; o <<= 1) {
            int v = __shfl_up_sync(~0u, sc, o);
            if (lane >= o) sc += v;
        }
        if (lane == 31) swsum[wid] = sc;
        __syncthreads();
        if (wid == 0) {
            int v = (lane < 32) ? swsum[lane] : 0;
            int s = v;
            #pragma unroll
            for (int o = 1; o < 32; o <<= 1) {
                int x = __shfl_up_sync(~0u, s, o);
                if (lane >= o) s += x;
            }
            swsum[lane] = s - v;          // exclusive warp offsets
            if (lane == 31) s_b1 = -1;    // sentinel; also compute grand total below
        }
        __syncthreads();
        int before = sc - tot + swsum[wid];     // count in all higher bins
        int grand  = swsum[31] + __shfl_sync(~0u, sc, 31, 32); // not valid per-warp; recompute:
        // grand total = last thread's before+tot; broadcast via smem
        if (tid == NT - 1) hist[2048] = before + tot;   // reuse hist tail as scratch
        __syncthreads();
        grand = hist[2048];
        if (grand < K) {
            if (tid == 0) { s_T = 1u; s_need = 0; s_v2 = 0.f; s_b1 = -1; }
        } else if (before < K && before + tot >= K) {   // unique owner thread
            if (before + c0 >= K) { s_b1 = 2047 - 2 * tid; s_cA = before; }
            else                  { s_b1 = 2046 - 2 * tid; s_cA = before + c0; }
        }
        __syncthreads();
    }
    const int b1 = s_b1;

    if (b1 >= 0) {
        // ---------- level 2: 4096 bins over bits[19:8] within bin b1 ----------
        for (int i = tid; i < 4096; i += NT) hist[i] = 0;
        __syncthreads();
        for (int i = tid; i < N; i += NT) {
            unsigned u = base[i];
            if (u && (int)(u >> 20) == b1) {
                int bin = (u >> 8) & 0xFFF;
                unsigned peers = __match_any_sync(__activemask(), bin);
                if ((int)(__ffs(peers) - 1) == lane)
                    atomicAdd(&hist[bin], __popc(peers));
            }
        }
        __syncthreads();

        // suffix scan, 4 bins/thread: thread t covers 4095-4t .. 4092-4t
        {
            const int K2 = K - s_cA;      // >= 1, crossing guaranteed inside b1
            int c[4], tot = 0;
            #pragma unroll
            for (int q = 0; q < 4; q++) { c[q] = hist[4095 - 4 * tid - q]; tot += c[q]; }
            int sc = tot;
            #pragma unroll
            for (int o = 1; o < 32; o <<= 1) {
                int v = __shfl_up_sync(~0u, sc, o);
                if (lane >= o) sc += v;
            }
            if (lane == 31) swsum[wid] = sc;
            __syncthreads();
            if (wid == 0) {
                int v = (lane < 32) ? swsum[lane] : 0;
                int s = v;
                #pragma unroll
                for (int o = 1; o < 32; o <<= 1) {
                    int x = __shfl_up_sync(~0u, s, o);
                    if (lane >= o) s += x;
                }
                swsum[lane] = s - v;
            }
            __syncthreads();
            int before = sc - tot + swsum[wid];
            if (before < K2 && before + tot >= K2) {    // unique owner
                int acc = before, b2 = 4095 - 4 * tid, cSA = before;
                #pragma unroll
                for (int q = 0; q < 4; q++) {
                    if (acc + c[q] >= K2) { b2 = 4095 - 4 * tid - q; cSA = acc; break; }
                    acc += c[q];
                }
                s_need = K2 - cSA;
                s_T = ((unsigned)b1 << 20) + (((unsigned)b2 + 1u) << 8); // strictly above sub-bin
                // boundary values share 24 leading bits -> midpoint error < 2^-16 rel
                s_v2 = __uint_as_float(((unsigned)b1 << 20) | ((unsigned)b2 << 8) | 0x80u);
            }
            __syncthreads();
        }
    }

    // ---------- sum values strictly above threshold, plus `need` boundary values ----------
    const unsigned T = s_T;
    float sum = 0.f;
    for (int i = tid; i < N; i += NT) {
        unsigned u = base[i];
        if (u >= T) sum += __uint_as_float(u);
    }
    #pragma unroll
    for (int o = 16; o; o >>= 1) sum += __shfl_down_sync(~0u, sum, o);
    if (lane == 0) sred[wid] = sum;
    __syncthreads();
    if (wid == 0) {
        sum = (lane < 32) ? sred[lane] : 0.f;
        #pragma unroll
        for (int o = 16; o; o >>= 1) sum += __shfl_down_sync(~0u, sum, o);
        if (lane == 0) atomicAdd(&g_acc, (double)(sum + (float)s_need * s_v2));
    }
}

__global__ void fin_kernel(float* out) {
    out[0] = (float)(g_acc * (1.0 / 64.0));
}

extern "C" void kernel_launch(void* const* d_in, const int* in_sizes, int n_in,
                              void* d_out, int out_size)
{
    // identify inputs by element count (robust to metadata ordering)
    const float *pred0 = nullptr, *pred1 = nullptr, *pred2 = nullptr, *gtb = nullptr;
    const int *gtl = nullptr;
    for (int i = 0; i < n_in; i++) {
        switch (in_sizes[i]) {
            case 25165824: pred0 = (const float*)d_in[i]; break;  // 64*24*128*128
            case 6291456:  pred1 = (const float*)d_in[i]; break;  // 64*24*64*64
            case 1572864:  pred2 = (const float*)d_in[i]; break;  // 64*24*32*32
            case 8192:     gtb   = (const float*)d_in[i]; break;  // 64*32*4
            case 2048:     gtl   = (const int*)d_in[i];   break;  // 64*32
            default: break;                                       // anchors: recomputed
        }
    }

    zero_kernel<<<1, 256>>>();
    match_all<<<dim3(84, BATCH), 256>>>(pred0, pred1, pred2, gtb, gtl);
    select_kernel<<<NGROUPS, 1024>>>();
    fin_kernel<<<1, 1>>>((float*)d_out);
}

// round 11
// speedup vs baseline: 2.2226x; 1.0519x over previous
#include <cuda_runtime.h>
#include <math.h>

#define BATCH   64
#define NGT     32
#define NTOT    64512
#define NGROUPS 192   // 3 scales * 64 images

// ---- scratch (no allocations allowed) ----
__device__ unsigned int g_negbits[BATCH * NTOT];   // 16.5 MB, fully rewritten each run
__device__ double       g_acc;
__device__ int          g_numpos[NGROUPS];
__device__ int          g_done;

__global__ void zero_kernel() {
    int t = threadIdx.x;
    if (t == 0) { g_acc = 0.0; g_done = 0; }
    if (t < NGROUPS) g_numpos[t] = 0;
}

__device__ __forceinline__ float smooth_l1(float x) {
    float ax = fabsf(x);
    return ax < 1.0f ? (0.5f * x) * x : ax - 0.5f;
}

// fast softplus(-|x|) = log(1 + exp(-|x|)); e in (0,1] so 1+e has no cancellation
__device__ __forceinline__ float softplus_nabs(float ax) {
    return __logf(1.0f + __expf(-ax));
}

// One thread handles the 3 anchors (a=0..2) at one grid position (h,w).
// Per-block: precompute clamped wy per (row, gt, anchor) + per-row GT bitmask.
template<int H, int W, int STRIDE, int OFF, int SCALE>
__device__ __forceinline__ void match_body(int bx, int b,
                                           const float* __restrict__ pred,
                                           const float* __restrict__ gtb,
                                           const int*   __restrict__ gtl)
{
    constexpr int HW   = H * W;
    constexpr int ROWS = 256 / W;           // rows covered by one block (2/4/8)
    const int tid = threadIdx.x;

    __shared__ float4   sgt[NGT];
    __shared__ float    sarea[NGT];
    __shared__ int      slab[NGT];
    __shared__ float    swy[ROWS][NGT][3];  // clamped y-overlap per anchor
    __shared__ unsigned smask[ROWS];        // GTs with nonzero y-overlap (largest anchor)
    __shared__ float    swarp[8];
    __shared__ int      swpos[8];

    const float fs = (float)STRIDE;
    const float hh[3]    = {1.5f * fs, 2.0f * fs, 2.5f * fs};       // exact fp32
    const float areaA[3] = {9.0f * fs * fs, 16.0f * fs * fs, 25.0f * fs * fs};

    if (tid < NGT) {
        float4 g = ((const float4*)gtb)[b * NGT + tid];
        sgt[tid]   = g;
        sarea[tid] = (g.z - g.x) * (g.w - g.y);
        slab[tid]  = gtl[b * NGT + tid];
    }
    if (tid < ROWS) smask[tid] = 0u;
    __syncthreads();

    // build wy table + row masks: ROWS*NGT <= 256 items, one per thread
    if (tid < ROWS * NGT) {
        const int r = tid / NGT, j = tid % NGT;
        const int hR = bx * ROWS + r;
        const float cyr = (hR + 0.5f) * fs;                         // exact fp32
        float4 g = sgt[j];
        bool any = false;
        #pragma unroll
        for (int a = 0; a < 3; a++) {
            float wy = fminf(cyr + hh[a], g.w) - fmaxf(cyr - hh[a], g.y);
            wy = fmaxf(wy, 0.f);
            swy[r][j][a] = wy;
            any |= (wy > 0.f);
        }
        if (any) atomicOr(&smask[r], 1u << j);
    }
    __syncthreads();

    const int pl = bx * 256 + tid;           // HW multiple of 256
    const int w  = pl % W;
    const int r  = tid / W;                  // local row (warp-uniform: W >= 32)
    const float cx = (w + 0.5f) * fs;        // exact fp32

    const float x1a0 = cx - hh[0], x2a0 = cx + hh[0];
    const float x1a1 = cx - hh[1], x2a1 = cx + hh[1];
    const float x1a2 = cx - hh[2], x2a2 = cx + hh[2];

    // best per anchor: inter, denom (incl +1e-9), gt index
    float bI[3] = {0.f, 0.f, 0.f};
    float bD[3] = {1.f, 1.f, 1.f};
    int   bJ[3] = {0, 0, 0};

    unsigned m = smask[r];
    while (m) {
        const int j = __ffs(m) - 1;
        m &= m - 1;
        float4 g = sgt[j];
        // x-cull with the largest anchor (smaller anchors nested at same center)
        float wx2 = fminf(x2a2, g.z) - fmaxf(x1a2, g.x);
        if (wx2 > 0.f) {
            const float ab = sarea[j];
            const float x1s[3] = {x1a0, x1a1, x1a2};
            const float x2s[3] = {x2a0, x2a1, x2a2};
            #pragma unroll
            for (int a = 0; a < 3; a++) {
                float wx = fminf(x2s[a], g.z) - fmaxf(x1s[a], g.x);
                float inter = fmaxf(wx, 0.f) * swy[r][j][a];
                // same evaluation order as reference: ((aA + aB) - inter) + 1e-9
                float d = ((areaA[a] + ab) - inter) + 1e-9f;
                if (inter * bD[a] > bI[a] * d) { bI[a] = inter; bD[a] = d; bJ[a] = j; }
            }
        }
    }

    float lsum = 0.f;
    int   pcount = 0;
    const float* pb = pred + (size_t)b * 24 * HW + pl;

    #pragma unroll
    for (int a = 0; a < 3; a++) {
        float iou = bI[a] / bD[a];          // IEEE div, matches reference rounding
        bool pos = (iou >= 0.5f);
        bool neg = (iou <  0.4f);

        float x  = pb[(a * 8 + 4) * HW];
        float sp = softplus_nabs(fabsf(x));
        float Lneg = fmaxf(x, 0.f) + sp;    // BCE with target 0 (ranking value)
        g_negbits[b * NTOT + OFF + a * HW + pl] = neg ? __float_as_uint(Lneg) : 0u;

        if (pos) {
            pcount++;
            lsum += fmaxf(x, 0.f) - x + sp; // BCE with target 1

            float4 mb = sgt[bJ[a]];
            float sa = (3.0f + a) * fs;     // aw == ah == anchor size (exact)
            float gx = (mb.x + mb.z) * 0.5f;
            float gy = (mb.y + mb.w) * 0.5f;
            float gw = fmaxf(mb.z - mb.x, 1e-6f);
            float gh = fmaxf(mb.w - mb.y, 1e-6f);
            const int hR = bx * ROWS + r;
            float cy = (hR + 0.5f) * fs;
            float ttx = (gx - cx) / sa;
            float tty = (gy - cy) / sa;
            float ttw = logf(gw / sa);
            float tth = logf(gh / sa);

            float p0 = pb[(a * 8 + 0) * HW];
            float p1 = pb[(a * 8 + 1) * HW];
            float p2 = pb[(a * 8 + 2) * HW];
            float p3 = pb[(a * 8 + 3) * HW];
            lsum += smooth_l1(p0 - ttx) + smooth_l1(p1 - tty)
                  + smooth_l1(p2 - ttw) + smooth_l1(p3 - tth);

            float q0 = pb[(a * 8 + 5) * HW];
            float q1 = pb[(a * 8 + 6) * HW];
            float q2 = pb[(a * 8 + 7) * HW];
            float mm = fmaxf(q0, fmaxf(q1, q2));
            float lse = mm + logf(expf(q0 - mm) + expf(q1 - mm) + expf(q2 - mm));
            int lab = max(slab[bJ[a]], 0);
            float psel = (lab == 0) ? q0 : ((lab == 1) ? q1 : q2);
            lsum += lse - psel;
        }
    }

    // block reduce (256 threads = 8 warps)
    int lane = tid & 31, wid = tid >> 5;
    #pragma unroll
    for (int o = 16; o; o >>= 1) {
        lsum   += __shfl_down_sync(~0u, lsum, o);
        pcount += __shfl_down_sync(~0u, pcount, o);
    }
    if (lane == 0) { swarp[wid] = lsum; swpos[wid] = pcount; }
    __syncthreads();
    if (wid == 0) {
        lsum   = (lane < 8) ? swarp[lane] : 0.f;
        pcount = (lane < 8) ? swpos[lane] : 0;
        #pragma unroll
        for (int o = 4; o; o >>= 1) {
            lsum   += __shfl_down_sync(~0u, lsum, o);
            pcount += __shfl_down_sync(~0u, pcount, o);
        }
        if (lane == 0) {
            if (lsum != 0.f) atomicAdd(&g_acc, (double)lsum);
            if (pcount)      atomicAdd(&g_numpos[SCALE * BATCH + b], pcount);
        }
    }
}

// Fused: all three scales in one launch so scale-1/2 fill SMs alongside scale-0.
// blockIdx.x: [0,64) scale0, [64,80) scale1, [80,84) scale2.
__global__ void __launch_bounds__(256) match_all(const float* __restrict__ p0,
                                                 const float* __restrict__ p1,
                                                 const float* __restrict__ p2,
                                                 const float* __restrict__ gtb,
                                                 const int*   __restrict__ gtl)
{
    const int bx = blockIdx.x, b = blockIdx.y;
    if (bx < 64)      match_body<128, 128,  8,     0, 0>(bx,      b, p0, gtb, gtl);
    else if (bx < 80) match_body< 64,  64, 16, 49152, 1>(bx - 64, b, p1, gtb, gtl);
    else              match_body< 32,  32, 32, 61440, 2>(bx - 80, b, p2, gtb, gtl);
}

// Per (image, scale) hard-negative top-K sum via 2-level radix select on
// positive-float bit patterns. 1 block per group; data is L2/L1-resident.
// Histogram atomics are warp-aggregated; boundary search is a parallel
// block suffix-scan. The LAST block to finish also emits the final output
// (fin kernel folded in).
__global__ void __launch_bounds__(1024) select_kernel(float* __restrict__ out)
{
    const int g = blockIdx.x;             // 0..191
    const int scale = g / BATCH;
    const int b     = g % BATCH;
    const int Ns[3]   = {49152, 12288, 3072};
    const int Offs[3] = {0, 49152, 61440};
    const int N   = Ns[scale];
    const int off = Offs[scale];
    const unsigned* base = g_negbits + b * NTOT + off;
    const int K = 3 * max(1, g_numpos[g]);

    __shared__ int      hist[4096];
    __shared__ int      swsum[32];
    __shared__ unsigned s_T;
    __shared__ int      s_need, s_b1, s_cA;
    __shared__ float    s_v2;
    __shared__ float    sred[32];

    const int tid  = threadIdx.x;
    const int lane = tid & 31;
    const int wid  = tid >> 5;
    const int NT   = 1024;

    // ---------- level 1: 2048 bins over bits[31:20] ----------
    for (int i = tid; i < 2048; i += NT) hist[i] = 0;
    __syncthreads();
    for (int i = tid; i < N; i += NT) {
        unsigned u = base[i];
        if (u) {
            int bin = u >> 20;
            unsigned peers = __match_any_sync(__activemask(), bin);
            if ((int)(__ffs(peers) - 1) == lane)
                atomicAdd(&hist[bin], __popc(peers));
        }
    }
    __syncthreads();

    // suffix scan (descending bins), 2 bins/thread: thread t covers 2047-2t, 2046-2t
    {
        int c0 = hist[2047 - 2 * tid];
        int c1 = hist[2046 - 2 * tid];
        int tot = c0 + c1;
        // inclusive warp scan in t-order (== descending bin order)
        int sc = tot;
        #pragma unroll
        for (int o = 1; o < 32; o <<= 1) {
            int v = __shfl_up_sync(~0u, sc, o);
            if (lane >= o) sc += v;
        }
        if (lane == 31) swsum[wid] = sc;
        __syncthreads();
        if (wid == 0) {
            int v = (lane < 32) ? swsum[lane] : 0;
            int s = v;
            #pragma unroll
            for (int o = 1; o < 32; o <<= 1) {
                int x = __shfl_up_sync(~0u, s, o);
                if (lane >= o) s += x;
            }
            swsum[lane] = s - v;          // exclusive warp offsets
            if (lane == 31) s_b1 = -1;    // sentinel
        }
        __syncthreads();
        int before = sc - tot + swsum[wid];     // count in all higher bins
        if (tid == NT - 1) hist[2048] = before + tot;   // grand total, smem scratch
        __syncthreads();
        int grand = hist[2048];
        if (grand < K) {
            if (tid == 0) { s_T = 1u; s_need = 0; s_v2 = 0.f; s_b1 = -1; }
        } else if (before < K && before + tot >= K) {   // unique owner thread
            if (before + c0 >= K) { s_b1 = 2047 - 2 * tid; s_cA = before; }
            else                  { s_b1 = 2046 - 2 * tid; s_cA = before + c0; }
        }
        __syncthreads();
    }
    const int b1 = s_b1;

    if (b1 >= 0) {
        // ---------- level 2: 4096 bins over bits[19:8] within bin b1 ----------
        for (int i = tid; i < 4096; i += NT) hist[i] = 0;
        __syncthreads();
        for (int i = tid; i < N; i += NT) {
            unsigned u = base[i];
            if (u && (int)(u >> 20) == b1) {
                int bin = (u >> 8) & 0xFFF;
                unsigned peers = __match_any_sync(__activemask(), bin);
                if ((int)(__ffs(peers) - 1) == lane)
                    atomicAdd(&hist[bin], __popc(peers));
            }
        }
        __syncthreads();

        // suffix scan, 4 bins/thread: thread t covers 4095-4t .. 4092-4t
        {
            const int K2 = K - s_cA;      // >= 1, crossing guaranteed inside b1
            int c[4], tot = 0;
            #pragma unroll
            for (int q = 0; q < 4; q++) { c[q] = hist[4095 - 4 * tid - q]; tot += c[q]; }
            int sc = tot;
            #pragma unroll
            for (int o = 1; o < 32; o <<= 1) {
                int v = __shfl_up_sync(~0u, sc, o);
                if (lane >= o) sc += v;
            }
            if (lane == 31) swsum[wid] = sc;
            __syncthreads();
            if (wid == 0) {
                int v = (lane < 32) ? swsum[lane] : 0;
                int s = v;
                #pragma unroll
                for (int o = 1; o < 32; o <<= 1) {
                    int x = __shfl_up_sync(~0u, s, o);
                    if (lane >= o) s += x;
                }
                swsum[lane] = s - v;
            }
            __syncthreads();
            int before = sc - tot + swsum[wid];
            if (before < K2 && before + tot >= K2) {    // unique owner
                int acc = before, b2 = 4095 - 4 * tid, cSA = before;
                #pragma unroll
                for (int q = 0; q < 4; q++) {
                    if (acc + c[q] >= K2) { b2 = 4095 - 4 * tid - q; cSA = acc; break; }
                    acc += c[q];
                }
                s_need = K2 - cSA;
                s_T = ((unsigned)b1 << 20) + (((unsigned)b2 + 1u) << 8); // strictly above sub-bin
                // boundary values share 24 leading bits -> midpoint error < 2^-16 rel
                s_v2 = __uint_as_float(((unsigned)b1 << 20) | ((unsigned)b2 << 8) | 0x80u);
            }
            __syncthreads();
        }
    }

    // ---------- sum values strictly above threshold, plus `need` boundary values ----------
    const unsigned T = s_T;
    float sum = 0.f;
    for (int i = tid; i < N; i += NT) {
        unsigned u = base[i];
        if (u >= T) sum += __uint_as_float(u);
    }
    #pragma unroll
    for (int o = 16; o; o >>= 1) sum += __shfl_down_sync(~0u, sum, o);
    if (lane == 0) sred[wid] = sum;
    __syncthreads();
    if (wid == 0) {
        sum = (lane < 32) ? sred[lane] : 0.f;
        #pragma unroll
        for (int o = 16; o; o >>= 1) sum += __shfl_down_sync(~0u, sum, o);
        if (lane == 0) {
            atomicAdd(&g_acc, (double)(sum + (float)s_need * s_v2));
            // folded finalization: last block to complete writes the output
            __threadfence();
            int done = atomicAdd(&g_done, 1);
            if (done == NGROUPS - 1) {
                double total = atomicAdd(&g_acc, 0.0);   // coherent read after fence
                out[0] = (float)(total * (1.0 / 64.0));
            }
        }
    }
}

extern "C" void kernel_launch(void* const* d_in, const int* in_sizes, int n_in,
                              void* d_out, int out_size)
{
    // identify inputs by element count (robust to metadata ordering)
    const float *pred0 = nullptr, *pred1 = nullptr, *pred2 = nullptr, *gtb = nullptr;
    const int *gtl = nullptr;
    for (int i = 0; i < n_in; i++) {
        switch (in_sizes[i]) {
            case 25165824: pred0 = (const float*)d_in[i]; break;  // 64*24*128*128
            case 6291456:  pred1 = (const float*)d_in[i]; break;  // 64*24*64*64
            case 1572864:  pred2 = (const float*)d_in[i]; break;  // 64*24*32*32
            case 8192:     gtb   = (const float*)d_in[i]; break;  // 64*32*4
            case 2048:     gtl   = (const int*)d_in[i];   break;  // 64*32
            default: break;                                       // anchors: recomputed
        }
    }

    zero_kernel<<<1, 256>>>();
    match_all<<<dim3(84, BATCH), 256>>>(pred0, pred1, pred2, gtb, gtl);
    select_kernel<<<NGROUPS, 1024>>>((float*)d_out);
}